// round 4
// baseline (speedup 1.0000x reference)
#include <cuda_runtime.h>
#include <cstdint>

#define D_FEAT    128
#define MAX_NODES 65536
#define MAX_EDGES 1100000
#define BIN_CAP   96        // slots per node; Poisson(16) max-degree << 96

// ---------------- static device scratch (allocation-free, zero-initialized) --
__device__ int  g_cursor[MAX_NODES];            // starts 0; gather re-zeros
__device__ int2 g_slots[MAX_NODES * BIN_CAP];   // {src, float_as_int(val)}
__device__ int  g_over_cnt;
__device__ int  g_over_edges[MAX_EDGES];

// ---------------------------------------------------------------------------
// 0) zero overflow counter only (cursors are maintained zero by gather)
// ---------------------------------------------------------------------------
__global__ void prezero_kernel() {
    if (threadIdx.x == 0) g_over_cnt = 0;
}

// ---------------------------------------------------------------------------
// 1) bin edges by dst: 4 edges/thread, vectorized index loads for MLP
// ---------------------------------------------------------------------------
__device__ __forceinline__ void bin_one(int s, int d, float v, int eid) {
    int pos = atomicAdd(&g_cursor[d], 1);
    if (pos < BIN_CAP)
        g_slots[d * BIN_CAP + pos] = make_int2(s, __float_as_int(v));
    else
        g_over_edges[atomicAdd(&g_over_cnt, 1)] = eid;
}

__global__ void fill_kernel(const int*   __restrict__ src,
                            const int*   __restrict__ dst,
                            const float* __restrict__ vals,
                            int n_edges)
{
    int i = blockIdx.x * blockDim.x + threadIdx.x;
    int e = i * 4;
    if (e + 3 < n_edges) {
        int4   s4 = __ldg((const int4*)  (src  + e));
        int4   d4 = __ldg((const int4*)  (dst  + e));
        float4 v4 = __ldg((const float4*)(vals + e));
        bin_one(s4.x, d4.x, v4.x, e + 0);
        bin_one(s4.y, d4.y, v4.y, e + 1);
        bin_one(s4.z, d4.z, v4.z, e + 2);
        bin_one(s4.w, d4.w, v4.w, e + 3);
    } else {
        for (int k = e; k < n_edges; ++k)
            bin_one(__ldg(&src[k]), __ldg(&dst[k]), __ldg(&vals[k]), k);
    }
}

// ---------------------------------------------------------------------------
// 2) warp-per-node gather: acc = bias + sum(val * feat[src]); plain store.
//    Also resets g_cursor[node] to 0 for the next graph replay.
// ---------------------------------------------------------------------------
__global__ void gather_kernel(const float4* __restrict__ feat4,
                              const float4* __restrict__ bias4,
                              float4* __restrict__ out4,
                              int n_rows)
{
    int gtid = blockIdx.x * blockDim.x + threadIdx.x;
    int node = gtid >> 5;
    int lane = gtid & 31;
    if (node >= n_rows) return;

    float4 acc = __ldg(&bias4[lane]);

    int cnt = g_cursor[node];
    if (lane == 0) g_cursor[node] = 0;          // restore invariant
    cnt = min(cnt, BIN_CAP);
    const int2* bin = g_slots + (size_t)node * BIN_CAP;

    int e = 0;
    for (; e + 1 < cnt; e += 2) {
        int2 sv0 = __ldg(&bin[e]);
        int2 sv1 = __ldg(&bin[e + 1]);
        float4 f0 = __ldg(&feat4[(size_t)sv0.x * 32 + lane]);
        float4 f1 = __ldg(&feat4[(size_t)sv1.x * 32 + lane]);
        float v0 = __int_as_float(sv0.y);
        float v1 = __int_as_float(sv1.y);
        acc.x = fmaf(v0, f0.x, acc.x);
        acc.y = fmaf(v0, f0.y, acc.y);
        acc.z = fmaf(v0, f0.z, acc.z);
        acc.w = fmaf(v0, f0.w, acc.w);
        acc.x = fmaf(v1, f1.x, acc.x);
        acc.y = fmaf(v1, f1.y, acc.y);
        acc.z = fmaf(v1, f1.z, acc.z);
        acc.w = fmaf(v1, f1.w, acc.w);
    }
    if (e < cnt) {
        int2 sv = __ldg(&bin[e]);
        float4 f = __ldg(&feat4[(size_t)sv.x * 32 + lane]);
        float v = __int_as_float(sv.y);
        acc.x = fmaf(v, f.x, acc.x);
        acc.y = fmaf(v, f.y, acc.y);
        acc.z = fmaf(v, f.z, acc.z);
        acc.w = fmaf(v, f.w, acc.w);
    }

    out4[(size_t)node * 32 + lane] = acc;
}

// ---------------------------------------------------------------------------
// 3) overflow edges (empty in practice): small grid-stride RED scatter
// ---------------------------------------------------------------------------
__global__ void overflow_kernel(const int*   __restrict__ src,
                                const float* __restrict__ vals,
                                const float* __restrict__ feat,
                                float* __restrict__ out,
                                const int*   __restrict__ dst)
{
    int cnt = g_over_cnt;
    if (cnt == 0) return;
    long long total = (long long)cnt * 32;
    long long stride = (long long)gridDim.x * blockDim.x;
    for (long long w = blockIdx.x * (long long)blockDim.x + threadIdx.x;
         w < total; w += stride) {
        int slot = (int)(w >> 5);
        int lane = (int)(w & 31);
        int eid  = g_over_edges[slot];
        int s    = src[eid];
        int d    = dst[eid];
        float v  = vals[eid];
        const float4* frow = reinterpret_cast<const float4*>(feat + (size_t)s * D_FEAT);
        float4 f = __ldg(&frow[lane]);
        float4 m = make_float4(f.x * v, f.y * v, f.z * v, f.w * v);
        float* orow = out + (size_t)d * D_FEAT + lane * 4;
        asm volatile("red.global.add.v4.f32 [%0], {%1, %2, %3, %4};"
                     :: "l"(orow), "f"(m.x), "f"(m.y), "f"(m.z), "f"(m.w)
                     : "memory");
    }
}

// ---------------------------------------------------------------------------
// Fallback (R1 proven path) for shapes exceeding static scratch
// ---------------------------------------------------------------------------
__global__ void init_bias_kernel(float4* __restrict__ out,
                                 const float4* __restrict__ bias4,
                                 int total_vec4) {
    int idx = blockIdx.x * blockDim.x + threadIdx.x;
    if (idx >= total_vec4) return;
    out[idx] = __ldg(&bias4[idx & 31]);
}

__global__ void spmm_edge_kernel(const int* __restrict__ src,
                                 const int* __restrict__ dst,
                                 const float* __restrict__ vals,
                                 const float* __restrict__ feat,
                                 float* __restrict__ out,
                                 int n_edges) {
    int gtid = blockIdx.x * blockDim.x + threadIdx.x;
    int edge = gtid >> 5;
    int lane = gtid & 31;
    if (edge >= n_edges) return;

    int s = 0, d = 0;
    float v = 0.0f;
    if (lane == 0) { s = src[edge]; d = dst[edge]; v = vals[edge]; }
    s = __shfl_sync(0xffffffffu, s, 0);
    d = __shfl_sync(0xffffffffu, d, 0);
    v = __shfl_sync(0xffffffffu, v, 0);

    const float4* frow = reinterpret_cast<const float4*>(feat + (size_t)s * D_FEAT);
    float4 f = __ldg(&frow[lane]);
    float4 m = make_float4(f.x * v, f.y * v, f.z * v, f.w * v);

    float* orow = out + (size_t)d * D_FEAT + lane * 4;
    asm volatile("red.global.add.v4.f32 [%0], {%1, %2, %3, %4};"
                 :: "l"(orow), "f"(m.x), "f"(m.y), "f"(m.z), "f"(m.w)
                 : "memory");
}

// ---------------------------------------------------------------------------
// Launch.  d_in[0]=edge_index(2E i32: src then dst)  d_in[1]=edge_vals(E f32)
//          d_in[2]=features(N*128 f32)               d_in[3]=bias(128 f32)
// ---------------------------------------------------------------------------
extern "C" void kernel_launch(void* const* d_in, const int* in_sizes, int n_in,
                              void* d_out, int out_size)
{
    const int*   edge_index = (const int*)d_in[0];
    const float* edge_vals  = (const float*)d_in[1];
    const float* features   = (const float*)d_in[2];
    const float* bias       = (const float*)d_in[3];
    float*       out        = (float*)d_out;

    int n_edges = in_sizes[1];
    int n_rows  = in_sizes[2] / D_FEAT;

    const int* src = edge_index;
    const int* dst = edge_index + n_edges;

    if (n_rows <= MAX_NODES && n_edges <= MAX_EDGES) {
        prezero_kernel<<<1, 32>>>();
        {   // bin edges, 4 per thread
            int th = 256;
            int work = (n_edges + 3) / 4;
            int bl = (work + th - 1) / th;
            fill_kernel<<<bl, th>>>(src, dst, edge_vals, n_edges);
        }
        {   // gather, warp per node
            int th = 384;
            long long total = (long long)n_rows * 32;
            int bl = (int)((total + th - 1) / th);
            gather_kernel<<<bl, th>>>((const float4*)features,
                                      (const float4*)bias,
                                      (float4*)out, n_rows);
        }
        overflow_kernel<<<16, 256>>>(src, edge_vals, features, out, dst);
    } else {
        {   // fallback: bias init + atomic scatter
            int total_vec4 = n_rows * (D_FEAT / 4);
            int th = 256, bl = (total_vec4 + th - 1) / th;
            init_bias_kernel<<<bl, th>>>((float4*)out, (const float4*)bias,
                                         total_vec4);
        }
        {
            int th = 256;
            long long total = (long long)n_edges * 32;
            int bl = (int)((total + th - 1) / th);
            spmm_edge_kernel<<<bl, th>>>(src, dst, edge_vals, features, out,
                                         n_edges);
        }
    }
}

// round 5
// speedup vs baseline: 2.0897x; 2.0897x over previous
#include <cuda_runtime.h>
#include <cstdint>

#define D_FEAT    128
#define MAX_NODES 65536
#define MAX_EDGES 1100000
#define BIN_CAP   96        // slots per node; Poisson(16) max-degree << 96

// ---------------- static device scratch (allocation-free) -------------------
__device__ int  g_cursor[MAX_NODES];
__device__ int2 g_slots[MAX_NODES * BIN_CAP];   // {src, float_as_int(val)}
__device__ int  g_over_cnt;
__device__ int  g_over_edges[MAX_EDGES];

// ---------------------------------------------------------------------------
// 1) zero per-node cursors + overflow counter
// ---------------------------------------------------------------------------
__global__ void zero_kernel(int n_rows) {
    int i = blockIdx.x * blockDim.x + threadIdx.x;
    if (i < n_rows) g_cursor[i] = 0;
    if (i == 0)     g_over_cnt = 0;
}

// ---------------------------------------------------------------------------
// 2) bin edges by dst: ONE edge per thread — maximum warps in flight to hide
//    the ~320-cycle L2 atomic-return latency (fill is latency-bound).
// ---------------------------------------------------------------------------
__global__ void fill_kernel(const int*   __restrict__ src,
                            const int*   __restrict__ dst,
                            const float* __restrict__ vals,
                            int n_edges)
{
    int e = blockIdx.x * blockDim.x + threadIdx.x;
    if (e >= n_edges) return;
    int d   = __ldg(&dst[e]);
    int s   = __ldg(&src[e]);
    float v = __ldg(&vals[e]);
    int pos = atomicAdd(&g_cursor[d], 1);
    if (pos < BIN_CAP)
        g_slots[d * BIN_CAP + pos] = make_int2(s, __float_as_int(v));
    else
        g_over_edges[atomicAdd(&g_over_cnt, 1)] = e;
}

// ---------------------------------------------------------------------------
// 3) warp-per-node gather: acc = bias + sum(val * feat[src]); plain store
// ---------------------------------------------------------------------------
__global__ void gather_kernel(const float4* __restrict__ feat4,
                              const float4* __restrict__ bias4,
                              float4* __restrict__ out4,
                              int n_rows)
{
    int gtid = blockIdx.x * blockDim.x + threadIdx.x;
    int node = gtid >> 5;
    int lane = gtid & 31;
    if (node >= n_rows) return;

    float4 acc = __ldg(&bias4[lane]);

    int cnt = g_cursor[node];
    cnt = min(cnt, BIN_CAP);
    const int2* bin = g_slots + (size_t)node * BIN_CAP;

    int e = 0;
    for (; e + 1 < cnt; e += 2) {
        int2 sv0 = __ldg(&bin[e]);
        int2 sv1 = __ldg(&bin[e + 1]);
        float4 f0 = __ldg(&feat4[(size_t)sv0.x * 32 + lane]);
        float4 f1 = __ldg(&feat4[(size_t)sv1.x * 32 + lane]);
        float v0 = __int_as_float(sv0.y);
        float v1 = __int_as_float(sv1.y);
        acc.x = fmaf(v0, f0.x, acc.x);
        acc.y = fmaf(v0, f0.y, acc.y);
        acc.z = fmaf(v0, f0.z, acc.z);
        acc.w = fmaf(v0, f0.w, acc.w);
        acc.x = fmaf(v1, f1.x, acc.x);
        acc.y = fmaf(v1, f1.y, acc.y);
        acc.z = fmaf(v1, f1.z, acc.z);
        acc.w = fmaf(v1, f1.w, acc.w);
    }
    if (e < cnt) {
        int2 sv = __ldg(&bin[e]);
        float4 f = __ldg(&feat4[(size_t)sv.x * 32 + lane]);
        float v = __int_as_float(sv.y);
        acc.x = fmaf(v, f.x, acc.x);
        acc.y = fmaf(v, f.y, acc.y);
        acc.z = fmaf(v, f.z, acc.z);
        acc.w = fmaf(v, f.w, acc.w);
    }

    out4[(size_t)node * 32 + lane] = acc;
}

// ---------------------------------------------------------------------------
// 4) overflow edges (empty in practice): grid-stride RED scatter
// ---------------------------------------------------------------------------
__global__ void overflow_kernel(const int*   __restrict__ src,
                                const float* __restrict__ vals,
                                const float* __restrict__ feat,
                                float* __restrict__ out,
                                const int*   __restrict__ dst)
{
    int cnt = g_over_cnt;
    if (cnt == 0) return;
    long long total = (long long)cnt * 32;
    long long stride = (long long)gridDim.x * blockDim.x;
    for (long long w = blockIdx.x * (long long)blockDim.x + threadIdx.x;
         w < total; w += stride) {
        int slot = (int)(w >> 5);
        int lane = (int)(w & 31);
        int eid  = g_over_edges[slot];
        int s    = src[eid];
        int d    = dst[eid];
        float v  = vals[eid];
        const float4* frow = reinterpret_cast<const float4*>(feat + (size_t)s * D_FEAT);
        float4 f = __ldg(&frow[lane]);
        float4 m = make_float4(f.x * v, f.y * v, f.z * v, f.w * v);
        float* orow = out + (size_t)d * D_FEAT + lane * 4;
        asm volatile("red.global.add.v4.f32 [%0], {%1, %2, %3, %4};"
                     :: "l"(orow), "f"(m.x), "f"(m.y), "f"(m.z), "f"(m.w)
                     : "memory");
    }
}

// ---------------------------------------------------------------------------
// Fallback (R1 proven path) for shapes exceeding static scratch
// ---------------------------------------------------------------------------
__global__ void init_bias_kernel(float4* __restrict__ out,
                                 const float4* __restrict__ bias4,
                                 int total_vec4) {
    int idx = blockIdx.x * blockDim.x + threadIdx.x;
    if (idx >= total_vec4) return;
    out[idx] = __ldg(&bias4[idx & 31]);
}

__global__ void spmm_edge_kernel(const int* __restrict__ src,
                                 const int* __restrict__ dst,
                                 const float* __restrict__ vals,
                                 const float* __restrict__ feat,
                                 float* __restrict__ out,
                                 int n_edges) {
    int gtid = blockIdx.x * blockDim.x + threadIdx.x;
    int edge = gtid >> 5;
    int lane = gtid & 31;
    if (edge >= n_edges) return;

    int s = 0, d = 0;
    float v = 0.0f;
    if (lane == 0) { s = src[edge]; d = dst[edge]; v = vals[edge]; }
    s = __shfl_sync(0xffffffffu, s, 0);
    d = __shfl_sync(0xffffffffu, d, 0);
    v = __shfl_sync(0xffffffffu, v, 0);

    const float4* frow = reinterpret_cast<const float4*>(feat + (size_t)s * D_FEAT);
    float4 f = __ldg(&frow[lane]);
    float4 m = make_float4(f.x * v, f.y * v, f.z * v, f.w * v);

    float* orow = out + (size_t)d * D_FEAT + lane * 4;
    asm volatile("red.global.add.v4.f32 [%0], {%1, %2, %3, %4};"
                 :: "l"(orow), "f"(m.x), "f"(m.y), "f"(m.z), "f"(m.w)
                 : "memory");
}

// ---------------------------------------------------------------------------
// Launch.  d_in[0]=edge_index(2E i32: src then dst)  d_in[1]=edge_vals(E f32)
//          d_in[2]=features(N*128 f32)               d_in[3]=bias(128 f32)
// ---------------------------------------------------------------------------
extern "C" void kernel_launch(void* const* d_in, const int* in_sizes, int n_in,
                              void* d_out, int out_size)
{
    const int*   edge_index = (const int*)d_in[0];
    const float* edge_vals  = (const float*)d_in[1];
    const float* features   = (const float*)d_in[2];
    const float* bias       = (const float*)d_in[3];
    float*       out        = (float*)d_out;

    int n_edges = in_sizes[1];
    int n_rows  = in_sizes[2] / D_FEAT;

    const int* src = edge_index;
    const int* dst = edge_index + n_edges;

    if (n_rows <= MAX_NODES && n_edges <= MAX_EDGES) {
        {   // 1) zero cursors + overflow counter
            int th = 256, bl = (n_rows + th - 1) / th;
            zero_kernel<<<bl, th>>>(n_rows);
        }
        {   // 2) bin edges, one per thread
            int th = 256, bl = (n_edges + th - 1) / th;
            fill_kernel<<<bl, th>>>(src, dst, edge_vals, n_edges);
        }
        {   // 3) gather, warp per node
            int th = 256;
            long long total = (long long)n_rows * 32;
            int bl = (int)((total + th - 1) / th);
            gather_kernel<<<bl, th>>>((const float4*)features,
                                      (const float4*)bias,
                                      (float4*)out, n_rows);
        }
        // 4) overflow drain (expected empty; cost is fixed launch overhead)
        overflow_kernel<<<64, 256>>>(src, edge_vals, features, out, dst);
    } else {
        {   // fallback: bias init + atomic scatter
            int total_vec4 = n_rows * (D_FEAT / 4);
            int th = 256, bl = (total_vec4 + th - 1) / th;
            init_bias_kernel<<<bl, th>>>((float4*)out, (const float4*)bias,
                                         total_vec4);
        }
        {
            int th = 256;
            long long total = (long long)n_edges * 32;
            int bl = (int)((total + th - 1) / th);
            spmm_edge_kernel<<<bl, th>>>(src, dst, edge_vals, features, out,
                                         n_edges);
        }
    }
}

// round 6
// speedup vs baseline: 2.1923x; 1.0491x over previous
#include <cuda_runtime.h>
#include <cstdint>

#define D_FEAT    128
#define MAX_NODES 65536
#define MAX_EDGES 1100000
#define BIN_CAP   96        // slots per node; Poisson(16) max-degree << 96

// ---------------- static device scratch (allocation-free) -------------------
__device__ int  g_cursor[MAX_NODES];
__device__ int2 g_slots[MAX_NODES * BIN_CAP];   // {src, float_as_int(val)}
__device__ int  g_over_cnt;
__device__ int  g_over_edges[MAX_EDGES];

// ---------------------------------------------------------------------------
// 1) zero per-node cursors + overflow counter
// ---------------------------------------------------------------------------
__global__ void zero_kernel(int n_rows) {
    int i = blockIdx.x * blockDim.x + threadIdx.x;
    if (i < n_rows) g_cursor[i] = 0;
    if (i == 0)     g_over_cnt = 0;
}

// ---------------------------------------------------------------------------
// 2) bin edges by dst: one edge per thread (proven R5 config)
// ---------------------------------------------------------------------------
__global__ void fill_kernel(const int*   __restrict__ src,
                            const int*   __restrict__ dst,
                            const float* __restrict__ vals,
                            int n_edges)
{
    int e = blockIdx.x * blockDim.x + threadIdx.x;
    if (e >= n_edges) return;
    int d   = __ldg(&dst[e]);
    int s   = __ldg(&src[e]);
    float v = __ldg(&vals[e]);
    int pos = atomicAdd(&g_cursor[d], 1);
    if (pos < BIN_CAP)
        g_slots[d * BIN_CAP + pos] = make_int2(s, __float_as_int(v));
    else
        g_over_edges[atomicAdd(&g_over_cnt, 1)] = e;
}

// ---------------------------------------------------------------------------
// 3) warp-per-node gather: acc = bias + sum(val * feat[src]); plain store.
//    Unroll-4 with int4 slot loads for MLP; overflow drained in-kernel
//    (g_over_cnt is 0 in practice -> cost is one uniform load per warp).
// ---------------------------------------------------------------------------
__global__ void gather_kernel(const float4* __restrict__ feat4,
                              const float4* __restrict__ bias4,
                              float4* __restrict__ out4,
                              const int*   __restrict__ src,
                              const int*   __restrict__ dst,
                              const float* __restrict__ vals,
                              int n_rows)
{
    int gtid = blockIdx.x * blockDim.x + threadIdx.x;
    int node = gtid >> 5;
    int lane = gtid & 31;
    if (node >= n_rows) return;

    float4 acc = __ldg(&bias4[lane]);

    int cnt = g_cursor[node];
    cnt = min(cnt, BIN_CAP);
    const int2* bin = g_slots + (size_t)node * BIN_CAP;

    int e = 0;
    // unroll 4: two int4 slot loads + four independent feature-row loads
    for (; e + 3 < cnt; e += 4) {
        int4 p01 = __ldg((const int4*)(bin + e));       // slots e, e+1
        int4 p23 = __ldg((const int4*)(bin + e + 2));   // slots e+2, e+3
        float4 f0 = __ldg(&feat4[(size_t)p01.x * 32 + lane]);
        float4 f1 = __ldg(&feat4[(size_t)p01.z * 32 + lane]);
        float4 f2 = __ldg(&feat4[(size_t)p23.x * 32 + lane]);
        float4 f3 = __ldg(&feat4[(size_t)p23.z * 32 + lane]);
        float v0 = __int_as_float(p01.y);
        float v1 = __int_as_float(p01.w);
        float v2 = __int_as_float(p23.y);
        float v3 = __int_as_float(p23.w);
        acc.x = fmaf(v0, f0.x, acc.x); acc.y = fmaf(v0, f0.y, acc.y);
        acc.z = fmaf(v0, f0.z, acc.z); acc.w = fmaf(v0, f0.w, acc.w);
        acc.x = fmaf(v1, f1.x, acc.x); acc.y = fmaf(v1, f1.y, acc.y);
        acc.z = fmaf(v1, f1.z, acc.z); acc.w = fmaf(v1, f1.w, acc.w);
        acc.x = fmaf(v2, f2.x, acc.x); acc.y = fmaf(v2, f2.y, acc.y);
        acc.z = fmaf(v2, f2.z, acc.z); acc.w = fmaf(v2, f2.w, acc.w);
        acc.x = fmaf(v3, f3.x, acc.x); acc.y = fmaf(v3, f3.y, acc.y);
        acc.z = fmaf(v3, f3.z, acc.z); acc.w = fmaf(v3, f3.w, acc.w);
    }
    for (; e < cnt; ++e) {
        int2 sv = __ldg(&bin[e]);
        float4 f = __ldg(&feat4[(size_t)sv.x * 32 + lane]);
        float v = __int_as_float(sv.y);
        acc.x = fmaf(v, f.x, acc.x); acc.y = fmaf(v, f.y, acc.y);
        acc.z = fmaf(v, f.z, acc.z); acc.w = fmaf(v, f.w, acc.w);
    }

    // overflow drain (expected 0): one uniform load; full scan only if nonzero
    int oc = g_over_cnt;
    if (oc != 0) {
        for (int i = 0; i < oc; ++i) {
            int eid = g_over_edges[i];
            if (__ldg(&dst[eid]) == node) {
                int s   = __ldg(&src[eid]);
                float v = __ldg(&vals[eid]);
                float4 f = __ldg(&feat4[(size_t)s * 32 + lane]);
                acc.x = fmaf(v, f.x, acc.x); acc.y = fmaf(v, f.y, acc.y);
                acc.z = fmaf(v, f.z, acc.z); acc.w = fmaf(v, f.w, acc.w);
            }
        }
    }

    out4[(size_t)node * 32 + lane] = acc;
}

// ---------------------------------------------------------------------------
// Fallback (R1 proven path) for shapes exceeding static scratch
// ---------------------------------------------------------------------------
__global__ void init_bias_kernel(float4* __restrict__ out,
                                 const float4* __restrict__ bias4,
                                 int total_vec4) {
    int idx = blockIdx.x * blockDim.x + threadIdx.x;
    if (idx >= total_vec4) return;
    out[idx] = __ldg(&bias4[idx & 31]);
}

__global__ void spmm_edge_kernel(const int* __restrict__ src,
                                 const int* __restrict__ dst,
                                 const float* __restrict__ vals,
                                 const float* __restrict__ feat,
                                 float* __restrict__ out,
                                 int n_edges) {
    int gtid = blockIdx.x * blockDim.x + threadIdx.x;
    int edge = gtid >> 5;
    int lane = gtid & 31;
    if (edge >= n_edges) return;

    int s = 0, d = 0;
    float v = 0.0f;
    if (lane == 0) { s = src[edge]; d = dst[edge]; v = vals[edge]; }
    s = __shfl_sync(0xffffffffu, s, 0);
    d = __shfl_sync(0xffffffffu, d, 0);
    v = __shfl_sync(0xffffffffu, v, 0);

    const float4* frow = reinterpret_cast<const float4*>(feat + (size_t)s * D_FEAT);
    float4 f = __ldg(&frow[lane]);
    float4 m = make_float4(f.x * v, f.y * v, f.z * v, f.w * v);

    float* orow = out + (size_t)d * D_FEAT + lane * 4;
    asm volatile("red.global.add.v4.f32 [%0], {%1, %2, %3, %4};"
                 :: "l"(orow), "f"(m.x), "f"(m.y), "f"(m.z), "f"(m.w)
                 : "memory");
}

// ---------------------------------------------------------------------------
// Launch.  d_in[0]=edge_index(2E i32: src then dst)  d_in[1]=edge_vals(E f32)
//          d_in[2]=features(N*128 f32)               d_in[3]=bias(128 f32)
// ---------------------------------------------------------------------------
extern "C" void kernel_launch(void* const* d_in, const int* in_sizes, int n_in,
                              void* d_out, int out_size)
{
    const int*   edge_index = (const int*)d_in[0];
    const float* edge_vals  = (const float*)d_in[1];
    const float* features   = (const float*)d_in[2];
    const float* bias       = (const float*)d_in[3];
    float*       out        = (float*)d_out;

    int n_edges = in_sizes[1];
    int n_rows  = in_sizes[2] / D_FEAT;

    const int* src = edge_index;
    const int* dst = edge_index + n_edges;

    if (n_rows <= MAX_NODES && n_edges <= MAX_EDGES) {
        {   // 1) zero cursors + overflow counter
            int th = 256, bl = (n_rows + th - 1) / th;
            zero_kernel<<<bl, th>>>(n_rows);
        }
        {   // 2) bin edges, one per thread
            int th = 256, bl = (n_edges + th - 1) / th;
            fill_kernel<<<bl, th>>>(src, dst, edge_vals, n_edges);
        }
        {   // 3) gather (warp per node) + in-kernel overflow drain
            int th = 256;
            long long total = (long long)n_rows * 32;
            int bl = (int)((total + th - 1) / th);
            gather_kernel<<<bl, th>>>((const float4*)features,
                                      (const float4*)bias,
                                      (float4*)out,
                                      src, dst, edge_vals, n_rows);
        }
    } else {
        {   // fallback: bias init + atomic scatter
            int total_vec4 = n_rows * (D_FEAT / 4);
            int th = 256, bl = (total_vec4 + th - 1) / th;
            init_bias_kernel<<<bl, th>>>((float4*)out, (const float4*)bias,
                                         total_vec4);
        }
        {
            int th = 256;
            long long total = (long long)n_edges * 32;
            int bl = (int)((total + th - 1) / th);
            spmm_edge_kernel<<<bl, th>>>(src, dst, edge_vals, features, out,
                                         n_edges);
        }
    }
}